// round 1
// baseline (speedup 1.0000x reference)
#include <cuda_runtime.h>
#include <cuda_bf16.h>

// Problem constants (fixed by the reference)
#define B 16
#define S 4096
#define H 768
#define NUM_WORDS 2048          // S/2
#define H4 (H / 4)              // 192 float4 lanes per row

// One block per (batch, word). word_ids within a row are non-decreasing over
// the valid region [1, S-1) (positions 0 and S-1 are -1 sentinels), so each
// word is a contiguous run of tokens. Binary-search the run, stream it with
// coalesced float4 loads, write the mean (zeros for empty words).
__global__ __launch_bounds__(H4) void word_mean_kernel(
    const float* __restrict__ hidden,   // [B, S, H]
    const int*   __restrict__ word_ids, // [B, S]
    float*       __restrict__ out)      // [B, NUM_WORDS, H]
{
    const int bw = blockIdx.x;
    const int b  = bw >> 11;            // / NUM_WORDS
    const int w  = bw & (NUM_WORDS - 1);

    const int* __restrict__ wrow = word_ids + b * S;

    // lower_bound for w over [1, S-1): first index with wrow[i] >= w
    int lo = 1, hi = S - 1;
    while (lo < hi) {
        int mid = (lo + hi) >> 1;
        if (wrow[mid] < w) lo = mid + 1; else hi = mid;
    }
    const int start = lo;

    // lower_bound for w+1: first index with wrow[i] >= w+1
    hi = S - 1;
    while (lo < hi) {
        int mid = (lo + hi) >> 1;
        if (wrow[mid] < w + 1) lo = mid + 1; else hi = mid;
    }
    const int end = lo;
    const int count = end - start;

    const int tid = threadIdx.x;        // 0..191
    const float4* __restrict__ hs4 =
        reinterpret_cast<const float4*>(hidden) + (size_t)b * S * H4 + tid;
    float4* __restrict__ out4 =
        reinterpret_cast<float4*>(out) + (size_t)bw * H4 + tid;

    if (count <= 0) {
        *out4 = make_float4(0.f, 0.f, 0.f, 0.f);
        return;
    }

    float4 acc = make_float4(0.f, 0.f, 0.f, 0.f);
    #pragma unroll 2
    for (int s = start; s < end; ++s) {
        float4 v = hs4[(size_t)s * H4];
        acc.x += v.x; acc.y += v.y; acc.z += v.z; acc.w += v.w;
    }
    const float inv = 1.0f / (float)count;
    acc.x *= inv; acc.y *= inv; acc.z *= inv; acc.w *= inv;
    *out4 = acc;
}

extern "C" void kernel_launch(void* const* d_in, const int* in_sizes, int n_in,
                              void* d_out, int out_size)
{
    const float* hidden   = (const float*)d_in[0];  // [B,S,H] float32
    const int*   word_ids = (const int*)d_in[1];    // [B,S] int32
    float*       out      = (float*)d_out;          // [B,NUM_WORDS,H] float32

    (void)in_sizes; (void)n_in; (void)out_size;

    word_mean_kernel<<<B * NUM_WORDS, H4>>>(hidden, word_ids, out);
}

// round 2
// speedup vs baseline: 1.6926x; 1.6926x over previous
#include <cuda_runtime.h>
#include <cuda_bf16.h>

// Problem constants (fixed by the reference)
#define B 16
#define S 4096
#define H 768
#define NUM_WORDS 2048          // S/2
#define H4 (H / 4)              // 192 float4 lanes per row

// Per-(b,word) token-run boundaries, filled by boundary_kernel each call.
// No init needed: words in [0, wmax] are guaranteed present (word ids are
// contiguous from 0), and words > wmax are handled without reading the table.
__device__ int g_start[B * NUM_WORDS];
__device__ int g_end[B * NUM_WORDS];

// Kernel A: one thread per interior token position i in [1, S-2].
// word_ids row layout: wrow[0] = -1, wrow[S-1] = -1, wrow[i] >= 0 otherwise,
// non-decreasing. Token i starts word w iff wrow[i-1] != w (sentinel at i=1
// makes this automatic); ends it iff wrow[i+1] != w.
__global__ __launch_bounds__(256) void boundary_kernel(
    const int* __restrict__ word_ids)   // [B, S]
{
    const int b = blockIdx.y;
    const int i = blockIdx.x * 256 + threadIdx.x + 1;   // 1 .. S-2
    if (i > S - 2) return;

    const int* __restrict__ wrow = word_ids + b * S;
    const int w     = wrow[i];
    const int wprev = wrow[i - 1];
    const int wnext = wrow[i + 1];

    if (wprev != w) g_start[b * NUM_WORDS + w] = i;
    if (wnext != w) g_end[b * NUM_WORDS + w]   = i + 1;
}

// Kernel B: one block per (batch, word). Read precomputed run bounds (L2-hot),
// stream the contiguous token run with coalesced float4 loads, write the mean.
__global__ __launch_bounds__(H4) void word_mean_kernel(
    const float* __restrict__ hidden,   // [B, S, H]
    const int*   __restrict__ word_ids, // [B, S]
    float*       __restrict__ out)      // [B, NUM_WORDS, H]
{
    const int bw = blockIdx.x;
    const int b  = bw >> 11;            // / NUM_WORDS
    const int w  = bw & (NUM_WORDS - 1);

    const int tid = threadIdx.x;        // 0..191
    float4* __restrict__ out4 =
        reinterpret_cast<float4*>(out) + (size_t)bw * H4 + tid;

    // Highest word id present in this row (last valid token).
    const int wmax = __ldg(word_ids + b * S + (S - 2));

    if (w > wmax) {
        *out4 = make_float4(0.f, 0.f, 0.f, 0.f);
        return;
    }

    const int start = g_start[bw];
    const int end   = g_end[bw];
    const int count = end - start;

    const float4* __restrict__ hs4 =
        reinterpret_cast<const float4*>(hidden) + (size_t)b * S * H4 + tid;

    float4 acc = make_float4(0.f, 0.f, 0.f, 0.f);
    #pragma unroll 2
    for (int s = start; s < end; ++s) {
        float4 v = hs4[(size_t)s * H4];
        acc.x += v.x; acc.y += v.y; acc.z += v.z; acc.w += v.w;
    }
    const float inv = 1.0f / (float)count;
    acc.x *= inv; acc.y *= inv; acc.z *= inv; acc.w *= inv;
    *out4 = acc;
}

extern "C" void kernel_launch(void* const* d_in, const int* in_sizes, int n_in,
                              void* d_out, int out_size)
{
    const float* hidden   = (const float*)d_in[0];  // [B,S,H] float32
    const int*   word_ids = (const int*)d_in[1];    // [B,S] int32
    float*       out      = (float*)d_out;          // [B,NUM_WORDS,H] float32

    (void)in_sizes; (void)n_in; (void)out_size;

    dim3 gridA((S - 2 + 255) / 256, B);
    boundary_kernel<<<gridA, 256>>>(word_ids);
    word_mean_kernel<<<B * NUM_WORDS, H4>>>(hidden, word_ids, out);
}

// round 3
// speedup vs baseline: 2.2822x; 1.3483x over previous
#include <cuda_runtime.h>
#include <cuda_bf16.h>

// Problem constants (fixed by the reference)
#define B 16
#define S 4096
#define H 768
#define NUM_WORDS 2048          // S/2
#define H4 (H / 4)              // 192 float4 lanes per row
#define W 8                     // words per block
#define G 8                     // tokens batch-loaded per group (MLP depth)

// Per-(b,word) token-run boundaries, filled by boundary_kernel each call.
__device__ int g_start[B * NUM_WORDS];
__device__ int g_end[B * NUM_WORDS];

// Kernel A: one thread per interior token position i in [1, S-2].
// word_ids row: wrow[0] = -1, wrow[S-1] = -1, non-decreasing contiguous in between.
__global__ __launch_bounds__(256) void boundary_kernel(
    const int* __restrict__ word_ids)   // [B, S]
{
    const int b = blockIdx.y;
    const int i = blockIdx.x * 256 + threadIdx.x + 1;   // 1 .. S-2
    if (i > S - 2) return;

    const int* __restrict__ wrow = word_ids + b * S;
    const int w     = wrow[i];
    const int wprev = wrow[i - 1];
    const int wnext = wrow[i + 1];

    if (wprev != w) g_start[b * NUM_WORDS + w] = i;
    if (wnext != w) g_end[b * NUM_WORDS + w]   = i + 1;
}

// Kernel B: one block per (batch, chunk of W consecutive words). The W words'
// tokens form one contiguous run [s0, e_last). Stream it with groups of G
// front-batched float4 loads (high per-warp MLP), routing tokens to word
// accumulators via uniform shared-memory boundaries.
__global__ __launch_bounds__(H4) void word_mean_kernel(
    const float* __restrict__ hidden,   // [B, S, H]
    const int*   __restrict__ word_ids, // [B, S]
    float*       __restrict__ out)      // [B, NUM_WORDS, H]
{
    const int blk = blockIdx.x;
    const int b   = blk / (NUM_WORDS / W);
    const int wc  = blk % (NUM_WORDS / W);
    const int w0  = wc * W;
    const int tid = threadIdx.x;        // 0..191

    float4* __restrict__ outBase =
        reinterpret_cast<float4*>(out) + (size_t)(b * NUM_WORDS + w0) * H4 + tid;

    // Highest word id present in this row.
    const int wmax = __ldg(word_ids + b * S + (S - 2));

    if (w0 > wmax) {
        const float4 z = make_float4(0.f, 0.f, 0.f, 0.f);
        #pragma unroll
        for (int k = 0; k < W; ++k) outBase[k * H4] = z;
        return;
    }

    // Uniform per-block word-end table. Words past wmax clamp to wmax's end,
    // making their runs empty (count 0 -> zeros).
    __shared__ int s_end[W];
    if (tid < W) {
        int ww = w0 + tid;
        if (ww > wmax) ww = wmax;
        s_end[tid] = g_end[b * NUM_WORDS + ww];
    }
    __syncthreads();

    const int s0     = g_start[b * NUM_WORDS + w0];
    const int e_last = s_end[W - 1];

    const float4* __restrict__ hs4 =
        reinterpret_cast<const float4*>(hidden) + (size_t)b * S * H4 + tid;

    int k = 0;
    int e_cur = s_end[0];
    int s_cur = s0;
    float4 acc = make_float4(0.f, 0.f, 0.f, 0.f);

    for (int t = s0; t < e_last; t += G) {
        // Batch-issue up to G independent coalesced float4 loads.
        float4 v[G];
        #pragma unroll
        for (int j = 0; j < G; ++j)
            if (t + j < e_last) v[j] = hs4[(size_t)(t + j) * H4];

        // Route each token to its word (boundaries uniform across the warp).
        #pragma unroll
        for (int j = 0; j < G; ++j) {
            if (t + j < e_last) {
                if (t + j == e_cur) {    // word k complete -> emit mean
                    int c = e_cur - s_cur;
                    float inv = __fdividef(1.0f, (float)(c > 0 ? c : 1));
                    float4 r;
                    r.x = acc.x * inv; r.y = acc.y * inv;
                    r.z = acc.z * inv; r.w = acc.w * inv;
                    outBase[k * H4] = r;
                    s_cur = e_cur;
                    ++k;
                    e_cur = s_end[k];
                    acc = make_float4(0.f, 0.f, 0.f, 0.f);
                }
                acc.x += v[j].x; acc.y += v[j].y;
                acc.z += v[j].z; acc.w += v[j].w;
            }
        }
    }

    // Emit remaining words (last real word + any clamped empty trailing words).
    while (k < W) {
        int c = e_cur - s_cur;
        float inv = __fdividef(1.0f, (float)(c > 0 ? c : 1));
        float4 r;
        r.x = acc.x * inv; r.y = acc.y * inv;
        r.z = acc.z * inv; r.w = acc.w * inv;
        outBase[k * H4] = r;
        s_cur = e_cur;
        ++k;
        if (k < W) e_cur = s_end[k];
        acc = make_float4(0.f, 0.f, 0.f, 0.f);
    }
}

extern "C" void kernel_launch(void* const* d_in, const int* in_sizes, int n_in,
                              void* d_out, int out_size)
{
    const float* hidden   = (const float*)d_in[0];  // [B,S,H] float32
    const int*   word_ids = (const int*)d_in[1];    // [B,S] int32
    float*       out      = (float*)d_out;          // [B,NUM_WORDS,H] float32

    (void)in_sizes; (void)n_in; (void)out_size;

    dim3 gridA((S - 2 + 255) / 256, B);
    boundary_kernel<<<gridA, 256>>>(word_ids);
    word_mean_kernel<<<B * (NUM_WORDS / W), H4>>>(hidden, word_ids, out);
}